// round 6
// baseline (speedup 1.0000x reference)
#include <cuda_runtime.h>
#include <cstdint>

#define BB 4
#define NNODES 2048
#define DD 256
#define HH 8
#define HDIM 32
#define EE 65536
#define MASK_WORDS (NNODES / 32)   /* 64 */
#define MAXDEG 160
#define WPB 8                      /* warps per block in attn */

// ---------------- device scratch (no allocation allowed) ----------------
__device__ float g_Q[BB * NNODES * DD];
__device__ float g_K[BB * NNODES * DD];
__device__ float g_V[BB * NNODES * DD];
__device__ float g_att[BB * NNODES * DD];
__device__ unsigned int g_mask[NNODES * MASK_WORDS];

// ---------------- adjacency mask ----------------
__global__ void clear_mask_kernel() {
    int i = blockIdx.x * blockDim.x + threadIdx.x;
    if (i < NNODES * MASK_WORDS) g_mask[i] = 0u;
}

__global__ void build_mask_kernel(const int* __restrict__ edges) {
    int idx = blockIdx.x * blockDim.x + threadIdx.x;
    if (idx < EE) {
        int s = edges[idx];
        int d = edges[EE + idx];
        atomicOr(&g_mask[s * MASK_WORDS + (d >> 5)], 1u << (d & 31));
        atomicOr(&g_mask[d * MASK_WORDS + (s >> 5)], 1u << (s & 31));
    } else if (idx < EE + NNODES) {
        int i = idx - EE;
        atomicOr(&g_mask[i * MASK_WORDS + (i >> 5)], 1u << (i & 31));
    }
}

// ---------------- SGEMM: C[M,256] = A[M,256] @ W[256,256]^T + bias ----------------
__device__ __forceinline__ void sgemm_body(const float* __restrict__ A,
                                           const float* __restrict__ W,
                                           const float* __restrict__ bias,
                                           float* __restrict__ C) {
    __shared__ float As[16][128];
    __shared__ float Ws[16][64];

    const int tid = threadIdx.x;
    const int m0 = blockIdx.x * 128;
    const int n0 = blockIdx.y * 64;
    const int tm = tid >> 3;   // 0..15
    const int tn = tid & 7;    // 0..7
    const int wrow = tid & 63;
    const int wk = (tid >> 6) * 8;

    float acc[8][8];
#pragma unroll
    for (int i = 0; i < 8; i++)
#pragma unroll
        for (int j = 0; j < 8; j++) acc[i][j] = 0.f;

    for (int k0 = 0; k0 < 256; k0 += 16) {
        const float4* Ar = reinterpret_cast<const float4*>(A + (size_t)(m0 + tid) * 256 + k0);
        float4 a0 = Ar[0], a1 = Ar[1], a2 = Ar[2], a3 = Ar[3];
        const float4* Wr = reinterpret_cast<const float4*>(W + (size_t)(n0 + wrow) * 256 + k0 + wk);
        float4 w0 = Wr[0], w1 = Wr[1];

        __syncthreads();
        As[0][tid] = a0.x;  As[1][tid] = a0.y;  As[2][tid] = a0.z;  As[3][tid] = a0.w;
        As[4][tid] = a1.x;  As[5][tid] = a1.y;  As[6][tid] = a1.z;  As[7][tid] = a1.w;
        As[8][tid] = a2.x;  As[9][tid] = a2.y;  As[10][tid] = a2.z; As[11][tid] = a2.w;
        As[12][tid] = a3.x; As[13][tid] = a3.y; As[14][tid] = a3.z; As[15][tid] = a3.w;
        Ws[wk + 0][wrow] = w0.x; Ws[wk + 1][wrow] = w0.y;
        Ws[wk + 2][wrow] = w0.z; Ws[wk + 3][wrow] = w0.w;
        Ws[wk + 4][wrow] = w1.x; Ws[wk + 5][wrow] = w1.y;
        Ws[wk + 6][wrow] = w1.z; Ws[wk + 7][wrow] = w1.w;
        __syncthreads();

#pragma unroll
        for (int k = 0; k < 16; k++) {
            float4 aA = *reinterpret_cast<const float4*>(&As[k][tm * 8]);
            float4 aB = *reinterpret_cast<const float4*>(&As[k][tm * 8 + 4]);
            float4 bA = *reinterpret_cast<const float4*>(&Ws[k][tn * 8]);
            float4 bB = *reinterpret_cast<const float4*>(&Ws[k][tn * 8 + 4]);
            float a[8] = {aA.x, aA.y, aA.z, aA.w, aB.x, aB.y, aB.z, aB.w};
            float w[8] = {bA.x, bA.y, bA.z, bA.w, bB.x, bB.y, bB.z, bB.w};
#pragma unroll
            for (int i = 0; i < 8; i++)
#pragma unroll
                for (int j = 0; j < 8; j++) acc[i][j] += a[i] * w[j];
        }
    }

    float bs[8];
#pragma unroll
    for (int j = 0; j < 8; j++) bs[j] = bias[n0 + tn * 8 + j];

#pragma unroll
    for (int i = 0; i < 8; i++) {
        float* Cr = C + (size_t)(m0 + tm * 8 + i) * 256 + n0 + tn * 8;
        float4 o0, o1;
        o0.x = acc[i][0] + bs[0]; o0.y = acc[i][1] + bs[1];
        o0.z = acc[i][2] + bs[2]; o0.w = acc[i][3] + bs[3];
        o1.x = acc[i][4] + bs[4]; o1.y = acc[i][5] + bs[5];
        o1.z = acc[i][6] + bs[6]; o1.w = acc[i][7] + bs[7];
        reinterpret_cast<float4*>(Cr)[0] = o0;
        reinterpret_cast<float4*>(Cr)[1] = o1;
    }
}

__global__ void __launch_bounds__(128) qkv_kernel(const float* __restrict__ x,
                                                  const float* __restrict__ Wq, const float* __restrict__ bq,
                                                  const float* __restrict__ Wk, const float* __restrict__ bk,
                                                  const float* __restrict__ Wv, const float* __restrict__ bv) {
    const float* W; const float* bb; float* C;
    if (blockIdx.z == 0)      { W = Wq; bb = bq; C = g_Q; }
    else if (blockIdx.z == 1) { W = Wk; bb = bk; C = g_K; }
    else                      { W = Wv; bb = bv; C = g_V; }
    sgemm_body(x, W, bb, C);
}

__global__ void __launch_bounds__(128) oproj_kernel(const float* __restrict__ Wo,
                                                    const float* __restrict__ bo,
                                                    float* __restrict__ out) {
    sgemm_body(g_att, Wo, bo, out);
}

// ---------------- sparse masked attention (restructured) ----------------
// One warp per (b,i). Lane layout: h = lane>>2 (head), s = lane&3.
// Pass 1: each neighbor's K row (1KB) read fully-coalesced in one iteration;
//         per-head dot reduced with 2 shfl_xor. 2 neighbors in flight.
// Pass 2: lane owns dims [lane*8, lane*8+8) (head lane>>2); 2 float4 V loads
//         per neighbor, probability via smem broadcast.
__global__ void __launch_bounds__(32 * WPB) attn_kernel(const float* __restrict__ tptr,
                                                        float* __restrict__ attn_out) {
    __shared__ unsigned short s_idx[WPB][MAXDEG];
    __shared__ float s_sc[WPB][8][MAXDEG + 1];   // +1: avoid 8-way bank conflict on writes

    const int warp = threadIdx.x >> 5;
    const int lane = threadIdx.x & 31;
    const int flat = blockIdx.x * WPB + warp;        // 0 .. B*N-1
    const int b = flat >> 11;                        // / 2048
    const int i = flat & (NNODES - 1);
    const float invT = 1.0f / (*tptr);

    // --- enumerate neighbors from bitmask row i ---
    unsigned int w0 = g_mask[i * MASK_WORDS + lane];
    unsigned int w1 = g_mask[i * MASK_WORDS + 32 + lane];
    int c0 = __popc(w0), c1 = __popc(w1);

    int incl0 = c0;
#pragma unroll
    for (int d = 1; d < 32; d <<= 1) {
        int t = __shfl_up_sync(0xffffffffu, incl0, d);
        if (lane >= d) incl0 += t;
    }
    int tot0 = __shfl_sync(0xffffffffu, incl0, 31);
    int off0 = incl0 - c0;

    int incl1 = c1;
#pragma unroll
    for (int d = 1; d < 32; d <<= 1) {
        int t = __shfl_up_sync(0xffffffffu, incl1, d);
        if (lane >= d) incl1 += t;
    }
    int tot1 = __shfl_sync(0xffffffffu, incl1, 31);
    int off1 = tot0 + incl1 - c1;

    int deg = tot0 + tot1;
    if (deg > MAXDEG) deg = MAXDEG;   // unreachable for this input (max deg ~110)

    {
        int o = off0, base = lane * 32;
        while (w0) {
            int p = __ffs(w0) - 1; w0 &= w0 - 1;
            if (o < MAXDEG) s_idx[warp][o] = (unsigned short)(base + p);
            o++;
        }
        o = off1; base = 1024 + lane * 32;
        while (w1) {
            int p = __ffs(w1) - 1; w1 &= w1 - 1;
            if (o < MAXDEG) s_idx[warp][o] = (unsigned short)(base + p);
            o++;
        }
    }
    __syncwarp();

    const int h = lane >> 2;          // head handled by this lane's 4-group
    const int s = lane & 3;           // sub-slot within head
    const size_t rowbase = (size_t)(b * NNODES + i) * DD;
    const float* __restrict__ Kb = g_K + (size_t)b * NNODES * DD;
    const float* __restrict__ Vb = g_V + (size_t)b * NNODES * DD;

    // q fragment: dims h*32 + s*8 .. +7
    const float* Qrow = g_Q + rowbase + h * 32 + s * 8;
    const float4 qa = reinterpret_cast<const float4*>(Qrow)[0];
    const float4 qb = reinterpret_cast<const float4*>(Qrow)[1];

    // --- pass 1: scores, 2 neighbors per iteration ---
    for (int nb = 0; nb < deg; nb += 2) {
        const bool has1 = (nb + 1) < deg;
        const int j0 = s_idx[warp][nb];
        const int j1 = s_idx[warp][has1 ? nb + 1 : nb];
        const float* K0 = Kb + (size_t)j0 * DD + h * 32 + s * 8;
        const float* K1 = Kb + (size_t)j1 * DD + h * 32 + s * 8;
        float4 a0 = reinterpret_cast<const float4*>(K0)[0];
        float4 b0 = reinterpret_cast<const float4*>(K0)[1];
        float4 a1 = reinterpret_cast<const float4*>(K1)[0];
        float4 b1 = reinterpret_cast<const float4*>(K1)[1];
        float p0 = qa.x * a0.x + qa.y * a0.y + qa.z * a0.z + qa.w * a0.w
                 + qb.x * b0.x + qb.y * b0.y + qb.z * b0.z + qb.w * b0.w;
        float p1 = qa.x * a1.x + qa.y * a1.y + qa.z * a1.z + qa.w * a1.w
                 + qb.x * b1.x + qb.y * b1.y + qb.z * b1.z + qb.w * b1.w;
        p0 += __shfl_xor_sync(0xffffffffu, p0, 1);
        p0 += __shfl_xor_sync(0xffffffffu, p0, 2);
        p1 += __shfl_xor_sync(0xffffffffu, p1, 1);
        p1 += __shfl_xor_sync(0xffffffffu, p1, 2);
        if (s == 0) {
            s_sc[warp][h][nb] = p0 * invT;
            if (has1) s_sc[warp][h][nb + 1] = p1 * invT;
        }
    }
    __syncwarp();

    // --- softmax per head (4-lane group owns head h) ---
    {
        float m = -1e30f;
        for (int n = s; n < deg; n += 4) m = fmaxf(m, s_sc[warp][h][n]);
        m = fmaxf(m, __shfl_xor_sync(0xffffffffu, m, 1));
        m = fmaxf(m, __shfl_xor_sync(0xffffffffu, m, 2));
        float l = 0.f;
        for (int n = s; n < deg; n += 4) {
            float p = __expf(s_sc[warp][h][n] - m);
            s_sc[warp][h][n] = p;
            l += p;
        }
        l += __shfl_xor_sync(0xffffffffu, l, 1);
        l += __shfl_xor_sync(0xffffffffu, l, 2);
        const float inv_l = 1.0f / l;
        for (int n = s; n < deg; n += 4) s_sc[warp][h][n] *= inv_l;
    }
    __syncwarp();

    // --- attn_mean sparse scatter: lanes parallel over neighbors ---
    float* arow = attn_out + ((size_t)b * NNODES + i) * NNODES;
    for (int n = lane; n < deg; n += 32) {
        float ps = 0.f;
#pragma unroll
        for (int hh = 0; hh < 8; hh++) ps += s_sc[warp][hh][n];
        arow[s_idx[warp][n]] = ps * 0.125f;
    }

    // --- pass 2: attended = attn @ V, 2 neighbors per iteration ---
    float4 acca = {0.f, 0.f, 0.f, 0.f};
    float4 accb = {0.f, 0.f, 0.f, 0.f};
    for (int nb = 0; nb < deg; nb += 2) {
        const bool has1 = (nb + 1) < deg;
        const int j0 = s_idx[warp][nb];
        const int j1 = s_idx[warp][has1 ? nb + 1 : nb];
        const float* V0 = Vb + (size_t)j0 * DD + lane * 8;
        const float* V1 = Vb + (size_t)j1 * DD + lane * 8;
        float4 va0 = reinterpret_cast<const float4*>(V0)[0];
        float4 vb0 = reinterpret_cast<const float4*>(V0)[1];
        float4 va1 = reinterpret_cast<const float4*>(V1)[0];
        float4 vb1 = reinterpret_cast<const float4*>(V1)[1];
        const float p0 = s_sc[warp][h][nb];
        const float p1 = has1 ? s_sc[warp][h][nb + 1] : 0.f;
        acca.x += p0 * va0.x; acca.y += p0 * va0.y; acca.z += p0 * va0.z; acca.w += p0 * va0.w;
        accb.x += p0 * vb0.x; accb.y += p0 * vb0.y; accb.z += p0 * vb0.z; accb.w += p0 * vb0.w;
        acca.x += p1 * va1.x; acca.y += p1 * va1.y; acca.z += p1 * va1.z; acca.w += p1 * va1.w;
        accb.x += p1 * vb1.x; accb.y += p1 * vb1.y; accb.z += p1 * vb1.z; accb.w += p1 * vb1.w;
    }

    float* Ao = g_att + rowbase + lane * 8;
    reinterpret_cast<float4*>(Ao)[0] = acca;
    reinterpret_cast<float4*>(Ao)[1] = accb;
}

// ---------------- launch ----------------
extern "C" void kernel_launch(void* const* d_in, const int* in_sizes, int n_in,
                              void* d_out, int out_size) {
    const float* x  = (const float*)d_in[0];
    const int* edges = (const int*)d_in[1];
    const float* Wq = (const float*)d_in[2];
    const float* bq = (const float*)d_in[3];
    const float* Wk = (const float*)d_in[4];
    const float* bk = (const float*)d_in[5];
    const float* Wv = (const float*)d_in[6];
    const float* bv = (const float*)d_in[7];
    const float* Wo = (const float*)d_in[8];
    const float* bo = (const float*)d_in[9];
    const float* temp = (const float*)d_in[10];

    float* out = (float*)d_out;
    float* attn_out = out + (size_t)BB * NNODES * DD;

    // zero the dense attn_mean output (sparse scatter fills the rest)
    cudaMemsetAsync(attn_out, 0, (size_t)BB * NNODES * NNODES * sizeof(float), 0);

    clear_mask_kernel<<<(NNODES * MASK_WORDS + 255) / 256, 256>>>();
    build_mask_kernel<<<(EE + NNODES + 255) / 256, 256>>>(edges);

    dim3 gqkv(BB * NNODES / 128, DD / 64, 3);
    qkv_kernel<<<gqkv, 128>>>(x, Wq, bq, Wk, bk, Wv, bv);

    attn_kernel<<<BB * NNODES / WPB, 32 * WPB>>>(temp, attn_out);

    dim3 go(BB * NNODES / 128, DD / 64, 1);
    oproj_kernel<<<go, 128>>>(Wo, bo, out);
}

// round 8
// speedup vs baseline: 1.7717x; 1.7717x over previous
#include <cuda_runtime.h>
#include <cstdint>

#define BB 4
#define NNODES 2048
#define DD 256
#define HH 8
#define HDIM 32
#define EE 65536
#define MASK_WORDS (NNODES / 32)   /* 64 */
#define MAXDEG 128
#define WPB 8                      /* warps per block in attn */

// ---------------- device scratch (no allocation allowed) ----------------
__device__ float g_Q[BB * NNODES * DD];
__device__ float g_K[BB * NNODES * DD];
__device__ float g_V[BB * NNODES * DD];
__device__ float g_att[BB * NNODES * DD];
__device__ unsigned int g_mask[NNODES * MASK_WORDS];

// ---------------- adjacency mask ----------------
__global__ void build_mask_kernel(const int* __restrict__ edges) {
    int idx = blockIdx.x * blockDim.x + threadIdx.x;
    if (idx < EE) {
        int s = edges[idx];
        int d = edges[EE + idx];
        atomicOr(&g_mask[s * MASK_WORDS + (d >> 5)], 1u << (d & 31));
        atomicOr(&g_mask[d * MASK_WORDS + (s >> 5)], 1u << (s & 31));
    } else if (idx < EE + NNODES) {
        int i = idx - EE;
        atomicOr(&g_mask[i * MASK_WORDS + (i >> 5)], 1u << (i & 31));
    }
}

// ---------------- SGEMM: C[M,256] = A[M,256] @ W[256,256]^T + bias ----------------
// 256 threads, BM=128, BN=128, BK=16, 8x8 per-thread micro-tile.
__device__ __forceinline__ void sgemm_body(const float* __restrict__ A,
                                           const float* __restrict__ W,
                                           const float* __restrict__ bias,
                                           float* __restrict__ C) {
    __shared__ float As[16][128];
    __shared__ float Ws[16][128];

    const int tid = threadIdx.x;          // 0..255
    const int m0 = blockIdx.x * 128;
    const int n0 = blockIdx.y * 128;
    const int tx = tid & 15;              // 0..15 (N direction)
    const int ty = tid >> 4;              // 0..15 (M direction)
    const int lr = tid >> 1;              // load row 0..127
    const int lh = (tid & 1) * 8;         // k-half offset 0 or 8

    float acc[8][8];
#pragma unroll
    for (int i = 0; i < 8; i++)
#pragma unroll
        for (int j = 0; j < 8; j++) acc[i][j] = 0.f;

    const float* Ap = A + (size_t)(m0 + lr) * 256 + lh;
    const float* Wp = W + (size_t)(n0 + lr) * 256 + lh;

    for (int k0 = 0; k0 < 256; k0 += 16) {
        float4 a0 = reinterpret_cast<const float4*>(Ap + k0)[0];
        float4 a1 = reinterpret_cast<const float4*>(Ap + k0)[1];
        float4 w0 = reinterpret_cast<const float4*>(Wp + k0)[0];
        float4 w1 = reinterpret_cast<const float4*>(Wp + k0)[1];

        __syncthreads();   // previous iteration's readers done
        As[lh + 0][lr] = a0.x; As[lh + 1][lr] = a0.y; As[lh + 2][lr] = a0.z; As[lh + 3][lr] = a0.w;
        As[lh + 4][lr] = a1.x; As[lh + 5][lr] = a1.y; As[lh + 6][lr] = a1.z; As[lh + 7][lr] = a1.w;
        Ws[lh + 0][lr] = w0.x; Ws[lh + 1][lr] = w0.y; Ws[lh + 2][lr] = w0.z; Ws[lh + 3][lr] = w0.w;
        Ws[lh + 4][lr] = w1.x; Ws[lh + 5][lr] = w1.y; Ws[lh + 6][lr] = w1.z; Ws[lh + 7][lr] = w1.w;
        __syncthreads();

#pragma unroll
        for (int k = 0; k < 16; k++) {
            float4 aA = *reinterpret_cast<const float4*>(&As[k][ty * 8]);
            float4 aB = *reinterpret_cast<const float4*>(&As[k][ty * 8 + 4]);
            float4 bA = *reinterpret_cast<const float4*>(&Ws[k][tx * 8]);
            float4 bB = *reinterpret_cast<const float4*>(&Ws[k][tx * 8 + 4]);
            float a[8] = {aA.x, aA.y, aA.z, aA.w, aB.x, aB.y, aB.z, aB.w};
            float w[8] = {bA.x, bA.y, bA.z, bA.w, bB.x, bB.y, bB.z, bB.w};
#pragma unroll
            for (int i = 0; i < 8; i++)
#pragma unroll
                for (int j = 0; j < 8; j++) acc[i][j] += a[i] * w[j];
        }
    }

    float bs[8];
#pragma unroll
    for (int j = 0; j < 8; j++) bs[j] = bias[n0 + tx * 8 + j];

#pragma unroll
    for (int i = 0; i < 8; i++) {
        float* Cr = C + (size_t)(m0 + ty * 8 + i) * 256 + n0 + tx * 8;
        float4 o0, o1;
        o0.x = acc[i][0] + bs[0]; o0.y = acc[i][1] + bs[1];
        o0.z = acc[i][2] + bs[2]; o0.w = acc[i][3] + bs[3];
        o1.x = acc[i][4] + bs[4]; o1.y = acc[i][5] + bs[5];
        o1.z = acc[i][6] + bs[6]; o1.w = acc[i][7] + bs[7];
        reinterpret_cast<float4*>(Cr)[0] = o0;
        reinterpret_cast<float4*>(Cr)[1] = o1;
    }
}

__global__ void __launch_bounds__(256) qkv_kernel(const float* __restrict__ x,
                                                  const float* __restrict__ Wq, const float* __restrict__ bq,
                                                  const float* __restrict__ Wk, const float* __restrict__ bk,
                                                  const float* __restrict__ Wv, const float* __restrict__ bv) {
    const float* W; const float* bb; float* C;
    if (blockIdx.z == 0)      { W = Wq; bb = bq; C = g_Q; }
    else if (blockIdx.z == 1) { W = Wk; bb = bk; C = g_K; }
    else                      { W = Wv; bb = bv; C = g_V; }
    sgemm_body(x, W, bb, C);
}

__global__ void __launch_bounds__(256) oproj_kernel(const float* __restrict__ Wo,
                                                    const float* __restrict__ bo,
                                                    float* __restrict__ out) {
    sgemm_body(g_att, Wo, bo, out);
}

// ---------------- sparse masked attention ----------------
// One warp per (b,i). Lane layout: h = lane>>2 (head), s = lane&3.
// 4 neighbors in flight per iteration in both passes.
__global__ void __launch_bounds__(32 * WPB) attn_kernel(const float* __restrict__ tptr,
                                                        float* __restrict__ attn_out) {
    __shared__ unsigned short s_idx[WPB][MAXDEG];
    __shared__ float s_sc[WPB][8][MAXDEG + 1];   // +1 pad

    const int warp = threadIdx.x >> 5;
    const int lane = threadIdx.x & 31;
    const int flat = blockIdx.x * WPB + warp;        // 0 .. B*N-1
    const int b = flat >> 11;
    const int i = flat & (NNODES - 1);
    const float invT = 1.0f / (*tptr);

    // --- enumerate neighbors from bitmask row i ---
    unsigned int w0 = g_mask[i * MASK_WORDS + lane];
    unsigned int w1 = g_mask[i * MASK_WORDS + 32 + lane];
    int c0 = __popc(w0), c1 = __popc(w1);

    int incl0 = c0;
#pragma unroll
    for (int d = 1; d < 32; d <<= 1) {
        int t = __shfl_up_sync(0xffffffffu, incl0, d);
        if (lane >= d) incl0 += t;
    }
    int tot0 = __shfl_sync(0xffffffffu, incl0, 31);
    int off0 = incl0 - c0;

    int incl1 = c1;
#pragma unroll
    for (int d = 1; d < 32; d <<= 1) {
        int t = __shfl_up_sync(0xffffffffu, incl1, d);
        if (lane >= d) incl1 += t;
    }
    int tot1 = __shfl_sync(0xffffffffu, incl1, 31);
    int off1 = tot0 + incl1 - c1;

    int deg = tot0 + tot1;
    if (deg > MAXDEG) deg = MAXDEG;   // statistically unreachable (Poisson(64) tail)

    {
        int o = off0, base = lane * 32;
        while (w0) {
            int p = __ffs(w0) - 1; w0 &= w0 - 1;
            if (o < MAXDEG) s_idx[warp][o] = (unsigned short)(base + p);
            o++;
        }
        o = off1; base = 1024 + lane * 32;
        while (w1) {
            int p = __ffs(w1) - 1; w1 &= w1 - 1;
            if (o < MAXDEG) s_idx[warp][o] = (unsigned short)(base + p);
            o++;
        }
    }
    __syncwarp();

    const int h = lane >> 2;          // head owned by this 4-lane group
    const int s = lane & 3;
    const size_t rowbase = (size_t)(b * NNODES + i) * DD;
    const float* __restrict__ Kb = g_K + (size_t)b * NNODES * DD;
    const float* __restrict__ Vb = g_V + (size_t)b * NNODES * DD;

    const float* Qrow = g_Q + rowbase + h * 32 + s * 8;
    const float4 qa = reinterpret_cast<const float4*>(Qrow)[0];
    const float4 qb = reinterpret_cast<const float4*>(Qrow)[1];

    // --- pass 1: scores, 4 neighbors per iteration ---
    for (int nb = 0; nb < deg; nb += 4) {
        int n1 = (nb + 1 < deg) ? nb + 1 : deg - 1;
        int n2 = (nb + 2 < deg) ? nb + 2 : deg - 1;
        int n3 = (nb + 3 < deg) ? nb + 3 : deg - 1;
        const int j0 = s_idx[warp][nb];
        const int j1 = s_idx[warp][n1];
        const int j2 = s_idx[warp][n2];
        const int j3 = s_idx[warp][n3];
        const float* K0 = Kb + (size_t)j0 * DD + h * 32 + s * 8;
        const float* K1 = Kb + (size_t)j1 * DD + h * 32 + s * 8;
        const float* K2 = Kb + (size_t)j2 * DD + h * 32 + s * 8;
        const float* K3 = Kb + (size_t)j3 * DD + h * 32 + s * 8;
        float4 a0 = reinterpret_cast<const float4*>(K0)[0];
        float4 b0 = reinterpret_cast<const float4*>(K0)[1];
        float4 a1 = reinterpret_cast<const float4*>(K1)[0];
        float4 b1 = reinterpret_cast<const float4*>(K1)[1];
        float4 a2 = reinterpret_cast<const float4*>(K2)[0];
        float4 b2 = reinterpret_cast<const float4*>(K2)[1];
        float4 a3 = reinterpret_cast<const float4*>(K3)[0];
        float4 b3 = reinterpret_cast<const float4*>(K3)[1];
        float p0 = qa.x * a0.x + qa.y * a0.y + qa.z * a0.z + qa.w * a0.w
                 + qb.x * b0.x + qb.y * b0.y + qb.z * b0.z + qb.w * b0.w;
        float p1 = qa.x * a1.x + qa.y * a1.y + qa.z * a1.z + qa.w * a1.w
                 + qb.x * b1.x + qb.y * b1.y + qb.z * b1.z + qb.w * b1.w;
        float p2 = qa.x * a2.x + qa.y * a2.y + qa.z * a2.z + qa.w * a2.w
                 + qb.x * b2.x + qb.y * b2.y + qb.z * b2.z + qb.w * b2.w;
        float p3 = qa.x * a3.x + qa.y * a3.y + qa.z * a3.z + qa.w * a3.w
                 + qb.x * b3.x + qb.y * b3.y + qb.z * b3.z + qb.w * b3.w;
        p0 += __shfl_xor_sync(0xffffffffu, p0, 1);
        p0 += __shfl_xor_sync(0xffffffffu, p0, 2);
        p1 += __shfl_xor_sync(0xffffffffu, p1, 1);
        p1 += __shfl_xor_sync(0xffffffffu, p1, 2);
        p2 += __shfl_xor_sync(0xffffffffu, p2, 1);
        p2 += __shfl_xor_sync(0xffffffffu, p2, 2);
        p3 += __shfl_xor_sync(0xffffffffu, p3, 1);
        p3 += __shfl_xor_sync(0xffffffffu, p3, 2);
        if (s == 0) {
            s_sc[warp][h][nb] = p0 * invT;
            if (nb + 1 < deg) s_sc[warp][h][nb + 1] = p1 * invT;
            if (nb + 2 < deg) s_sc[warp][h][nb + 2] = p2 * invT;
            if (nb + 3 < deg) s_sc[warp][h][nb + 3] = p3 * invT;
        }
    }
    __syncwarp();

    // --- softmax per head (4-lane group owns head h) ---
    {
        float m = -1e30f;
        for (int n = s; n < deg; n += 4) m = fmaxf(m, s_sc[warp][h][n]);
        m = fmaxf(m, __shfl_xor_sync(0xffffffffu, m, 1));
        m = fmaxf(m, __shfl_xor_sync(0xffffffffu, m, 2));
        float l = 0.f;
        for (int n = s; n < deg; n += 4) {
            float p = __expf(s_sc[warp][h][n] - m);
            s_sc[warp][h][n] = p;
            l += p;
        }
        l += __shfl_xor_sync(0xffffffffu, l, 1);
        l += __shfl_xor_sync(0xffffffffu, l, 2);
        const float inv_l = 1.0f / l;
        for (int n = s; n < deg; n += 4) s_sc[warp][h][n] *= inv_l;
    }
    __syncwarp();

    // --- attn_mean sparse scatter: lanes parallel over neighbors ---
    float* arow = attn_out + ((size_t)b * NNODES + i) * NNODES;
    for (int n = lane; n < deg; n += 32) {
        float ps = 0.f;
#pragma unroll
        for (int hh = 0; hh < 8; hh++) ps += s_sc[warp][hh][n];
        arow[s_idx[warp][n]] = ps * 0.125f;
    }

    // --- pass 2: attended = attn @ V, 4 neighbors per iteration ---
    float4 acca = {0.f, 0.f, 0.f, 0.f};
    float4 accb = {0.f, 0.f, 0.f, 0.f};
    for (int nb = 0; nb < deg; nb += 4) {
        int n1 = (nb + 1 < deg) ? nb + 1 : deg - 1;
        int n2 = (nb + 2 < deg) ? nb + 2 : deg - 1;
        int n3 = (nb + 3 < deg) ? nb + 3 : deg - 1;
        const int j0 = s_idx[warp][nb];
        const int j1 = s_idx[warp][n1];
        const int j2 = s_idx[warp][n2];
        const int j3 = s_idx[warp][n3];
        const float* V0 = Vb + (size_t)j0 * DD + lane * 8;
        const float* V1 = Vb + (size_t)j1 * DD + lane * 8;
        const float* V2 = Vb + (size_t)j2 * DD + lane * 8;
        const float* V3 = Vb + (size_t)j3 * DD + lane * 8;
        float4 va0 = reinterpret_cast<const float4*>(V0)[0];
        float4 vb0 = reinterpret_cast<const float4*>(V0)[1];
        float4 va1 = reinterpret_cast<const float4*>(V1)[0];
        float4 vb1 = reinterpret_cast<const float4*>(V1)[1];
        float4 va2 = reinterpret_cast<const float4*>(V2)[0];
        float4 vb2 = reinterpret_cast<const float4*>(V2)[1];
        float4 va3 = reinterpret_cast<const float4*>(V3)[0];
        float4 vb3 = reinterpret_cast<const float4*>(V3)[1];
        const float p0 = s_sc[warp][h][nb];
        const float p1 = (nb + 1 < deg) ? s_sc[warp][h][nb + 1] : 0.f;
        const float p2 = (nb + 2 < deg) ? s_sc[warp][h][nb + 2] : 0.f;
        const float p3 = (nb + 3 < deg) ? s_sc[warp][h][nb + 3] : 0.f;
        acca.x += p0 * va0.x; acca.y += p0 * va0.y; acca.z += p0 * va0.z; acca.w += p0 * va0.w;
        accb.x += p0 * vb0.x; accb.y += p0 * vb0.y; accb.z += p0 * vb0.z; accb.w += p0 * vb0.w;
        acca.x += p1 * va1.x; acca.y += p1 * va1.y; acca.z += p1 * va1.z; acca.w += p1 * va1.w;
        accb.x += p1 * vb1.x; accb.y += p1 * vb1.y; accb.z += p1 * vb1.z; accb.w += p1 * vb1.w;
        acca.x += p2 * va2.x; acca.y += p2 * va2.y; acca.z += p2 * va2.z; acca.w += p2 * va2.w;
        accb.x += p2 * vb2.x; accb.y += p2 * vb2.y; accb.z += p2 * vb2.z; accb.w += p2 * vb2.w;
        acca.x += p3 * va3.x; acca.y += p3 * va3.y; acca.z += p3 * va3.z; acca.w += p3 * va3.w;
        accb.x += p3 * vb3.x; accb.y += p3 * vb3.y; accb.z += p3 * vb3.z; accb.w += p3 * vb3.w;
    }

    float* Ao = g_att + rowbase + lane * 8;
    reinterpret_cast<float4*>(Ao)[0] = acca;
    reinterpret_cast<float4*>(Ao)[1] = accb;
}

// ---------------- launch ----------------
extern "C" void kernel_launch(void* const* d_in, const int* in_sizes, int n_in,
                              void* d_out, int out_size) {
    const float* x  = (const float*)d_in[0];
    const int* edges = (const int*)d_in[1];
    const float* Wq = (const float*)d_in[2];
    const float* bq = (const float*)d_in[3];
    const float* Wk = (const float*)d_in[4];
    const float* bk = (const float*)d_in[5];
    const float* Wv = (const float*)d_in[6];
    const float* bv = (const float*)d_in[7];
    const float* Wo = (const float*)d_in[8];
    const float* bo = (const float*)d_in[9];
    const float* temp = (const float*)d_in[10];

    float* out = (float*)d_out;
    float* attn_out = out + (size_t)BB * NNODES * DD;

    void* maskp = nullptr;
    cudaGetSymbolAddress(&maskp, g_mask);

    cudaMemsetAsync(attn_out, 0, (size_t)BB * NNODES * NNODES * sizeof(float), 0);
    cudaMemsetAsync(maskp, 0, (size_t)NNODES * MASK_WORDS * sizeof(unsigned int), 0);

    build_mask_kernel<<<(EE + NNODES + 255) / 256, 256>>>(edges);

    dim3 gqkv(BB * NNODES / 128, DD / 128, 3);
    qkv_kernel<<<gqkv, 256>>>(x, Wq, bq, Wk, bk, Wv, bv);

    attn_kernel<<<BB * NNODES / WPB, 32 * WPB>>>(temp, attn_out);

    dim3 go(BB * NNODES / 128, DD / 128, 1);
    oproj_kernel<<<go, 256>>>(Wo, bo, out);
}